// round 7
// baseline (speedup 1.0000x reference)
#include <cuda_runtime.h>
#include <cuda_fp16.h>

#define BB 4
#define LL 1024
#define DD 64
#define UU 32
#define TI 4

// Scratch (allocation-free, __device__ globals)
__device__ __align__(16) uint4    g_kpt[4*BB*LL];     // [(b*4+cc)*1024+j]: u[cc*8..cc*8+7] half2-packed
__device__ __align__(16) unsigned g_qh [BB*LL*16];    // row*16+c : q u-pair (2c,2c+1) half2
__device__ __align__(16) __half   g_xt [BB*DD*LL];    // [b][d][j] fp16 transposed x   (512 KB)
__device__ __align__(16) __half   g_P  [BB*LL*LL];    // [row_global][j] fp16 exp(e)   (8 MB)
__device__            float       g_inv[BB*LL];       // 1/rowsum

__device__ __forceinline__ unsigned tanh2u(unsigned x) {
    unsigned y; asm("tanh.approx.f16x2 %0, %1;" : "=r"(y) : "r"(x)); return y;
}
__device__ __forceinline__ unsigned hadd2u(unsigned a, unsigned b) {
    __half2 r = __hadd2(reinterpret_cast<__half2&>(a), reinterpret_cast<__half2&>(b));
    return reinterpret_cast<unsigned&>(r);
}
__device__ __forceinline__ unsigned hfma2u(unsigned a, unsigned b, unsigned c) {
    __half2 r = __hfma2(reinterpret_cast<__half2&>(a), reinterpret_cast<__half2&>(b),
                        reinterpret_cast<__half2&>(c));
    return reinterpret_cast<unsigned&>(r);
}
__device__ __forceinline__ unsigned packh2(float a, float b) {
    __half2 h = __floats2half2_rn(a, b);
    return reinterpret_cast<unsigned&>(h);
}
__device__ __forceinline__ float2 h2f2(unsigned a) {
    return __half22float2(reinterpret_cast<__half2&>(a));
}

// ---------------------------------------------------------------------------
// Kernel 1: projections -> packed half scratch + transposed fp16 x.
// ---------------------------------------------------------------------------
__global__ __launch_bounds__(256) void prep_kernel(
    const float* __restrict__ x,
    const float* __restrict__ Wt,
    const float* __restrict__ Wx,
    const float* __restrict__ bh)
{
    __shared__ float sWt[DD*UU];
    __shared__ float sWx[DD*UU];
    __shared__ float sx [8*DD];
    __shared__ float sq [8][UU];
    __shared__ float sk [8][UU];
    int t = threadIdx.x;
    for (int idx = t; idx < DD*UU; idx += 256) { sWt[idx] = Wt[idx]; sWx[idx] = Wx[idx]; }
    int row0 = blockIdx.x * 8;
    for (int idx = t; idx < 8*DD; idx += 256) sx[idx] = x[row0*DD + idx];
    __syncthreads();

    int r = t >> 5, u = t & 31;
    float aq = 0.f, ak = 0.f;
    #pragma unroll
    for (int d = 0; d < DD; d++) {
        float xv = sx[r*DD + d];
        aq = fmaf(xv, sWt[d*UU + u], aq);
        ak = fmaf(xv, sWx[d*UU + u], ak);
    }
    sq[r][u] = aq;
    sk[r][u] = ak + bh[u];
    __syncthreads();

    int b  = row0 >> 10;
    int j0 = row0 & 1023;

    if (t < 128) {                        // pack q
        int rr = t >> 4, c = t & 15;
        g_qh[(row0 + rr)*16 + c] = packh2(sq[rr][2*c], sq[rr][2*c+1]);
    }
    if (t < 32) {                         // pack + transpose k'
        int rr = t >> 2, cc = t & 3;
        int j = j0 + rr;
        uint4 v;
        v.x = packh2(sk[rr][cc*8+0], sk[rr][cc*8+1]);
        v.y = packh2(sk[rr][cc*8+2], sk[rr][cc*8+3]);
        v.z = packh2(sk[rr][cc*8+4], sk[rr][cc*8+5]);
        v.w = packh2(sk[rr][cc*8+6], sk[rr][cc*8+7]);
        g_kpt[(b*4 + cc)*1024 + j] = v;
    }
    if (t < 64) {                         // transposed fp16 x: g_xt[b][d][j0..j0+7]
        int d = t;
        __half h[8];
        #pragma unroll
        for (int rr = 0; rr < 8; rr++) h[rr] = __float2half(sx[rr*DD + d]);
        *(uint4*)&g_xt[(b*DD + d)*LL + j0] = *(uint4*)h;
    }
}

// ---------------------------------------------------------------------------
// Kernel 2: scoring only. 4 rows per block; writes fp16 exp(e) + inv sums.
// ---------------------------------------------------------------------------
__global__ __launch_bounds__(256, 5) void score_kernel(
    const float* __restrict__ Wa)
{
    __shared__ unsigned swa2[16];
    __shared__ unsigned sq2[TI][16];
    __shared__ float    redv[TI][8];

    int t  = threadIdx.x;
    int bi = blockIdx.x;                  // 0..1023
    int b  = bi >> 8;
    int row0 = b*LL + (bi & 255)*TI;      // global row

    if (t < 16) swa2[t] = packh2(Wa[2*t], Wa[2*t+1]);
    if (t < 64) sq2[t >> 4][t & 15] = g_qh[(row0 + (t >> 4))*16 + (t & 15)];
    __syncthreads();

    const uint4* kp = g_kpt + (b*4)*1024;

    float acc_e[4][TI];                   // [jj][r]
    #pragma unroll
    for (int jj = 0; jj < 4; jj++)
        #pragma unroll
        for (int r = 0; r < TI; r++) acc_e[jj][r] = 0.f;

    uint4 kv = kp[t];                     // rolling 1-ahead prefetch
    #pragma unroll
    for (int cc = 0; cc < 4; cc++) {
        unsigned qc[TI][4], wc[4];
        #pragma unroll
        for (int k = 0; k < 4; k++) {
            wc[k] = swa2[cc*4 + k];
            #pragma unroll
            for (int r = 0; r < TI; r++) qc[r][k] = sq2[r][cc*4 + k];
        }
        #pragma unroll
        for (int jj = 0; jj < 4; jj++) {
            unsigned kw[4] = {kv.x, kv.y, kv.z, kv.w};
            int nit = cc*4 + jj + 1;
            if (nit < 16)
                kv = kp[(nit >> 2)*1024 + (nit & 3)*256 + t];
            #pragma unroll
            for (int r = 0; r < TI; r++) {
                unsigned hacc = 0u;
                #pragma unroll
                for (int k = 0; k < 4; k++)
                    hacc = hfma2u(tanh2u(hadd2u(qc[r][k], kw[k])), wc[k], hacc);
                float2 f = h2f2(hacc);
                acc_e[jj][r] += f.x + f.y;
            }
        }
    }

    float s[TI] = {0.f, 0.f, 0.f, 0.f};
    #pragma unroll
    for (int jj = 0; jj < 4; jj++) {
        int j = jj*256 + t;
        #pragma unroll
        for (int r = 0; r < TI; r++) {
            float ex = __expf(acc_e[jj][r]);     // |e| <= sum|Wa|: no max pass
            s[r] += ex;
            g_P[(row0 + r)*LL + j] = __float2half(ex);
        }
    }

    #pragma unroll
    for (int o = 16; o; o >>= 1)
        #pragma unroll
        for (int r = 0; r < TI; r++) s[r] += __shfl_xor_sync(0xffffffffu, s[r], o);
    if ((t & 31) == 0)
        #pragma unroll
        for (int r = 0; r < TI; r++) redv[r][t >> 5] = s[r];
    __syncthreads();
    if (t < TI) {
        float S = 0.f;
        #pragma unroll
        for (int w = 0; w < 8; w++) S += redv[t][w];
        g_inv[row0 + t] = 1.f / (S + 1e-8f);
    }
}

// ---------------------------------------------------------------------------
// Kernel 3: V = P @ X via HMMA m16n8k16, epilogue scales by inv.
// Block: 32 i-rows x 64 d for one b. 128 blocks, 256 threads (8 warps).
// ---------------------------------------------------------------------------
#define LDP 72   // padded half-stride (conflict-free LDS.32 frags)
__global__ __launch_bounds__(256) void gemm_kernel(float* __restrict__ out)
{
    __shared__ __half sP[32*LDP];
    __shared__ __half sX[64*LDP];
    __shared__ float  sInv[32];

    int t  = threadIdx.x;
    int bi = blockIdx.x;                  // 0..127
    int b  = bi >> 5;
    int i0 = (bi & 31) * 32;

    if (t < 32) sInv[t] = g_inv[b*LL + i0 + t];

    int warp = t >> 5, lane = t & 31;
    int g = lane >> 2, tg = lane & 3;
    int wi = warp >> 2, wd = warp & 3;    // 2 i-halves x 4 d-quarters

    float c[2][4] = {{0,0,0,0},{0,0,0,0}};

    const __half* Pg = g_P  + (size_t)(b*LL + i0)*LL;
    const __half* Xg = g_xt + (size_t)b*DD*LL;
    int prow = t >> 3, pcg = t & 7;

    for (int kc = 0; kc < 16; kc++) {
        int k0 = kc*64;
        __syncthreads();
        // stage P tile 32 x 64
        *(uint4*)&sP[prow*LDP + pcg*8] = *(const uint4*)&Pg[prow*LL + k0 + pcg*8];
        // stage Xt tile 64 x 64 (rows = d)
        #pragma unroll
        for (int it = 0; it < 2; it++) {
            int idx = t + it*256;
            int xr = idx >> 3, xcg = idx & 7;
            *(uint4*)&sX[xr*LDP + xcg*8] = *(const uint4*)&Xg[xr*LL + k0 + xcg*8];
        }
        __syncthreads();

        const unsigned* sP2 = (const unsigned*)sP;
        const unsigned* sX2 = (const unsigned*)sX;
        #pragma unroll
        for (int ks = 0; ks < 4; ks++) {
            int arow = wi*16 + g;
            int col  = ks*8 + tg;         // half2 index within row
            unsigned a0 = sP2[ arow   *(LDP/2) + col];
            unsigned a1 = sP2[(arow+8)*(LDP/2) + col];
            unsigned a2 = sP2[ arow   *(LDP/2) + col + 4];
            unsigned a3 = sP2[(arow+8)*(LDP/2) + col + 4];
            #pragma unroll
            for (int nh = 0; nh < 2; nh++) {
                int nrow = wd*16 + nh*8 + g;
                unsigned b0 = sX2[nrow*(LDP/2) + col];
                unsigned b1 = sX2[nrow*(LDP/2) + col + 4];
                asm volatile(
                    "mma.sync.aligned.m16n8k16.row.col.f32.f16.f16.f32 "
                    "{%0,%1,%2,%3}, {%4,%5,%6,%7}, {%8,%9}, {%0,%1,%2,%3};"
                    : "+f"(c[nh][0]), "+f"(c[nh][1]), "+f"(c[nh][2]), "+f"(c[nh][3])
                    : "r"(a0), "r"(a1), "r"(a2), "r"(a3), "r"(b0), "r"(b1));
            }
        }
    }

    // epilogue: scale by inv, store f32
    int irow = b*LL + i0 + wi*16 + g;
    float inv0 = sInv[wi*16 + g];
    float inv8 = sInv[wi*16 + g + 8];
    #pragma unroll
    for (int nh = 0; nh < 2; nh++) {
        int d = wd*16 + nh*8 + 2*tg;
        float2 v0 = { c[nh][0]*inv0, c[nh][1]*inv0 };
        float2 v1 = { c[nh][2]*inv8, c[nh][3]*inv8 };
        *(float2*)&out[(size_t) irow   *DD + d] = v0;
        *(float2*)&out[(size_t)(irow+8)*DD + d] = v1;
    }
}

// ---------------------------------------------------------------------------
extern "C" void kernel_launch(void* const* d_in, const int* in_sizes, int n_in,
                              void* d_out, int out_size)
{
    const float* x  = (const float*)d_in[0];
    const float* Wt = (const float*)d_in[1];
    const float* Wx = (const float*)d_in[2];
    const float* Wa = (const float*)d_in[3];
    const float* bh = (const float*)d_in[4];
    // d_in[5] = ba cancels in softmax; d_in[6] attention_width is dead code.

    prep_kernel <<<BB*LL/8, 256>>>(x, Wt, Wx, bh);
    score_kernel<<<BB*LL/TI, 256>>>(Wa);
    gemm_kernel <<<BB*LL/32, 256>>>((float*)d_out);
}

// round 8
// speedup vs baseline: 1.0078x; 1.0078x over previous
#include <cuda_runtime.h>
#include <cuda_fp16.h>

#define BB 4
#define LL 1024
#define DD 64
#define UU 32
#define TI 4

// Scratch (allocation-free, __device__ globals)
__device__ __align__(16) uint4    g_kpt[4*BB*LL];     // [(b*4+cc)*1024+j]: u[cc*8..cc*8+7] half2-packed
__device__ __align__(16) unsigned g_qh [BB*LL*16];    // row*16+c : q u-pair (2c,2c+1) half2
__device__ __align__(16) __half   g_xt [BB*DD*LL];    // [b][d][j] fp16 transposed x   (512 KB)
__device__ __align__(16) __half   g_P  [BB*LL*LL];    // [row_global][j] fp16 exp(e)   (8 MB)
__device__            float       g_inv[BB*LL];       // 1/rowsum

__device__ __forceinline__ unsigned tanh2u(unsigned x) {
    unsigned y; asm("tanh.approx.f16x2 %0, %1;" : "=r"(y) : "r"(x)); return y;
}
__device__ __forceinline__ unsigned hadd2u(unsigned a, unsigned b) {
    __half2 r = __hadd2(reinterpret_cast<__half2&>(a), reinterpret_cast<__half2&>(b));
    return reinterpret_cast<unsigned&>(r);
}
__device__ __forceinline__ unsigned hfma2u(unsigned a, unsigned b, unsigned c) {
    __half2 r = __hfma2(reinterpret_cast<__half2&>(a), reinterpret_cast<__half2&>(b),
                        reinterpret_cast<__half2&>(c));
    return reinterpret_cast<unsigned&>(r);
}
__device__ __forceinline__ unsigned packh2(float a, float b) {
    __half2 h = __floats2half2_rn(a, b);
    return reinterpret_cast<unsigned&>(h);
}
__device__ __forceinline__ float2 h2f2(unsigned a) {
    return __half22float2(reinterpret_cast<__half2&>(a));
}

// ---------------------------------------------------------------------------
// Kernel 1: projections -> packed half scratch + transposed fp16 x.
// ---------------------------------------------------------------------------
__global__ __launch_bounds__(256) void prep_kernel(
    const float* __restrict__ x,
    const float* __restrict__ Wt,
    const float* __restrict__ Wx,
    const float* __restrict__ bh)
{
    __shared__ float sWt[DD*UU];
    __shared__ float sWx[DD*UU];
    __shared__ float sx [8*DD];
    __shared__ float sq [8][UU];
    __shared__ float sk [8][UU];
    int t = threadIdx.x;
    for (int idx = t; idx < DD*UU; idx += 256) { sWt[idx] = Wt[idx]; sWx[idx] = Wx[idx]; }
    int row0 = blockIdx.x * 8;
    for (int idx = t; idx < 8*DD; idx += 256) sx[idx] = x[row0*DD + idx];
    __syncthreads();

    int r = t >> 5, u = t & 31;
    float aq = 0.f, ak = 0.f;
    #pragma unroll
    for (int d = 0; d < DD; d++) {
        float xv = sx[r*DD + d];
        aq = fmaf(xv, sWt[d*UU + u], aq);
        ak = fmaf(xv, sWx[d*UU + u], ak);
    }
    sq[r][u] = aq;
    sk[r][u] = ak + bh[u];
    __syncthreads();

    int b  = row0 >> 10;
    int j0 = row0 & 1023;

    if (t < 128) {                        // pack q
        int rr = t >> 4, c = t & 15;
        g_qh[(row0 + rr)*16 + c] = packh2(sq[rr][2*c], sq[rr][2*c+1]);
    }
    if (t < 32) {                         // pack + transpose k'
        int rr = t >> 2, cc = t & 3;
        int j = j0 + rr;
        uint4 v;
        v.x = packh2(sk[rr][cc*8+0], sk[rr][cc*8+1]);
        v.y = packh2(sk[rr][cc*8+2], sk[rr][cc*8+3]);
        v.z = packh2(sk[rr][cc*8+4], sk[rr][cc*8+5]);
        v.w = packh2(sk[rr][cc*8+6], sk[rr][cc*8+7]);
        g_kpt[(b*4 + cc)*1024 + j] = v;
    }
    if (t < 64) {                         // transposed fp16 x: g_xt[b][d][j0..j0+7]
        int d = t;
        __half h[8];
        #pragma unroll
        for (int rr = 0; rr < 8; rr++) h[rr] = __float2half(sx[rr*DD + d]);
        *(uint4*)&g_xt[(b*DD + d)*LL + j0] = *(uint4*)h;
    }
}

// ---------------------------------------------------------------------------
// Kernel 2: scoring only. 4 rows per block; writes fp16 exp(e) + inv sums.
// ---------------------------------------------------------------------------
__global__ __launch_bounds__(256, 5) void score_kernel(
    const float* __restrict__ Wa)
{
    __shared__ unsigned swa2[16];
    __shared__ unsigned sq2[TI][16];
    __shared__ float    redv[TI][8];

    int t  = threadIdx.x;
    int bi = blockIdx.x;                  // 0..1023
    int b  = bi >> 8;
    int row0 = b*LL + (bi & 255)*TI;      // global row

    if (t < 16) swa2[t] = packh2(Wa[2*t], Wa[2*t+1]);
    if (t < 64) sq2[t >> 4][t & 15] = g_qh[(row0 + (t >> 4))*16 + (t & 15)];
    __syncthreads();

    const uint4* kp = g_kpt + (b*4)*1024;

    float acc_e[4][TI];                   // [jj][r]
    #pragma unroll
    for (int jj = 0; jj < 4; jj++)
        #pragma unroll
        for (int r = 0; r < TI; r++) acc_e[jj][r] = 0.f;

    uint4 kv = kp[t];                     // rolling 1-ahead prefetch
    #pragma unroll
    for (int cc = 0; cc < 4; cc++) {
        unsigned qc[TI][4], wc[4];
        #pragma unroll
        for (int k = 0; k < 4; k++) {
            wc[k] = swa2[cc*4 + k];
            #pragma unroll
            for (int r = 0; r < TI; r++) qc[r][k] = sq2[r][cc*4 + k];
        }
        #pragma unroll
        for (int jj = 0; jj < 4; jj++) {
            unsigned kw[4] = {kv.x, kv.y, kv.z, kv.w};
            int nit = cc*4 + jj + 1;
            if (nit < 16)
                kv = kp[(nit >> 2)*1024 + (nit & 3)*256 + t];
            #pragma unroll
            for (int r = 0; r < TI; r++) {
                unsigned hacc = 0u;
                #pragma unroll
                for (int k = 0; k < 4; k++)
                    hacc = hfma2u(tanh2u(hadd2u(qc[r][k], kw[k])), wc[k], hacc);
                float2 f = h2f2(hacc);
                acc_e[jj][r] += f.x + f.y;
            }
        }
    }

    float s[TI] = {0.f, 0.f, 0.f, 0.f};
    #pragma unroll
    for (int jj = 0; jj < 4; jj++) {
        int j = jj*256 + t;
        #pragma unroll
        for (int r = 0; r < TI; r++) {
            float ex = __expf(acc_e[jj][r]);     // |e| <= sum|Wa|: no max pass
            s[r] += ex;
            g_P[(row0 + r)*LL + j] = __float2half(ex);
        }
    }

    #pragma unroll
    for (int o = 16; o; o >>= 1)
        #pragma unroll
        for (int r = 0; r < TI; r++) s[r] += __shfl_xor_sync(0xffffffffu, s[r], o);
    if ((t & 31) == 0)
        #pragma unroll
        for (int r = 0; r < TI; r++) redv[r][t >> 5] = s[r];
    __syncthreads();
    if (t < TI) {
        float S = 0.f;
        #pragma unroll
        for (int w = 0; w < 8; w++) S += redv[t][w];
        g_inv[row0 + t] = 1.f / (S + 1e-8f);
    }
}

// ---------------------------------------------------------------------------
// Kernel 3: V = P @ X via HMMA m16n8k16, epilogue scales by inv.
// Block: 32 i-rows x 64 d for one b. 128 blocks, 256 threads (8 warps).
// ---------------------------------------------------------------------------
#define LDP 72   // padded half-stride (conflict-free LDS.32 frags)
__global__ __launch_bounds__(256) void gemm_kernel(float* __restrict__ out)
{
    __shared__ __half sP[32*LDP];
    __shared__ __half sX[64*LDP];
    __shared__ float  sInv[32];

    int t  = threadIdx.x;
    int bi = blockIdx.x;                  // 0..127
    int b  = bi >> 5;
    int i0 = (bi & 31) * 32;

    if (t < 32) sInv[t] = g_inv[b*LL + i0 + t];

    int warp = t >> 5, lane = t & 31;
    int g = lane >> 2, tg = lane & 3;
    int wi = warp >> 2, wd = warp & 3;    // 2 i-halves x 4 d-quarters

    float c[2][4] = {{0,0,0,0},{0,0,0,0}};

    const __half* Pg = g_P  + (size_t)(b*LL + i0)*LL;
    const __half* Xg = g_xt + (size_t)b*DD*LL;
    int prow = t >> 3, pcg = t & 7;

    for (int kc = 0; kc < 16; kc++) {
        int k0 = kc*64;
        __syncthreads();
        // stage P tile 32 x 64
        *(uint4*)&sP[prow*LDP + pcg*8] = *(const uint4*)&Pg[prow*LL + k0 + pcg*8];
        // stage Xt tile 64 x 64 (rows = d)
        #pragma unroll
        for (int it = 0; it < 2; it++) {
            int idx = t + it*256;
            int xr = idx >> 3, xcg = idx & 7;
            *(uint4*)&sX[xr*LDP + xcg*8] = *(const uint4*)&Xg[xr*LL + k0 + xcg*8];
        }
        __syncthreads();

        const unsigned* sP2 = (const unsigned*)sP;
        const unsigned* sX2 = (const unsigned*)sX;
        #pragma unroll
        for (int ks = 0; ks < 4; ks++) {
            int arow = wi*16 + g;
            int col  = ks*8 + tg;         // half2 index within row
            unsigned a0 = sP2[ arow   *(LDP/2) + col];
            unsigned a1 = sP2[(arow+8)*(LDP/2) + col];
            unsigned a2 = sP2[ arow   *(LDP/2) + col + 4];
            unsigned a3 = sP2[(arow+8)*(LDP/2) + col + 4];
            #pragma unroll
            for (int nh = 0; nh < 2; nh++) {
                int nrow = wd*16 + nh*8 + g;
                unsigned b0 = sX2[nrow*(LDP/2) + col];
                unsigned b1 = sX2[nrow*(LDP/2) + col + 4];
                asm volatile(
                    "mma.sync.aligned.m16n8k16.row.col.f32.f16.f16.f32 "
                    "{%0,%1,%2,%3}, {%4,%5,%6,%7}, {%8,%9}, {%0,%1,%2,%3};"
                    : "+f"(c[nh][0]), "+f"(c[nh][1]), "+f"(c[nh][2]), "+f"(c[nh][3])
                    : "r"(a0), "r"(a1), "r"(a2), "r"(a3), "r"(b0), "r"(b1));
            }
        }
    }

    // epilogue: scale by inv, store f32
    int irow = b*LL + i0 + wi*16 + g;
    float inv0 = sInv[wi*16 + g];
    float inv8 = sInv[wi*16 + g + 8];
    #pragma unroll
    for (int nh = 0; nh < 2; nh++) {
        int d = wd*16 + nh*8 + 2*tg;
        float2 v0 = { c[nh][0]*inv0, c[nh][1]*inv0 };
        float2 v1 = { c[nh][2]*inv8, c[nh][3]*inv8 };
        *(float2*)&out[(size_t) irow   *DD + d] = v0;
        *(float2*)&out[(size_t)(irow+8)*DD + d] = v1;
    }
}

// ---------------------------------------------------------------------------
extern "C" void kernel_launch(void* const* d_in, const int* in_sizes, int n_in,
                              void* d_out, int out_size)
{
    const float* x  = (const float*)d_in[0];
    const float* Wt = (const float*)d_in[1];
    const float* Wx = (const float*)d_in[2];
    const float* Wa = (const float*)d_in[3];
    const float* bh = (const float*)d_in[4];
    // d_in[5] = ba cancels in softmax; d_in[6] attention_width is dead code.

    prep_kernel <<<BB*LL/8, 256>>>(x, Wt, Wx, bh);
    score_kernel<<<BB*LL/TI, 256>>>(Wa);
    gemm_kernel <<<BB*LL/32, 256>>>((float*)d_out);
}

// round 9
// speedup vs baseline: 1.0367x; 1.0287x over previous
#include <cuda_runtime.h>
#include <cuda_fp16.h>

#define BB 4
#define LL 1024
#define DD 64
#define UU 32
#define TI 2

// Scratch (allocation-free, __device__ globals)
__device__ __align__(16) uint4    g_kpt[4*BB*LL];     // [(b*4+cc)*1024+j]: u[cc*8..cc*8+7] half2-packed
__device__ __align__(16) unsigned g_qh [BB*LL*16];    // row*16+c : q u-pair (2c,2c+1) half2
__device__ __align__(16) __half   g_xt [BB*DD*LL];    // [b][d][j] fp16 transposed x   (512 KB)
__device__ __align__(16) __half   g_P  [BB*LL*LL];    // [row_global][j] fp16 exp(e)   (8 MB)
__device__            float       g_inv[BB*LL];       // 1/rowsum

__device__ __forceinline__ unsigned tanh2u(unsigned x) {
    unsigned y; asm("tanh.approx.f16x2 %0, %1;" : "=r"(y) : "r"(x)); return y;
}
__device__ __forceinline__ unsigned hadd2u(unsigned a, unsigned b) {
    __half2 r = __hadd2(reinterpret_cast<__half2&>(a), reinterpret_cast<__half2&>(b));
    return reinterpret_cast<unsigned&>(r);
}
__device__ __forceinline__ unsigned hfma2u(unsigned a, unsigned b, unsigned c) {
    __half2 r = __hfma2(reinterpret_cast<__half2&>(a), reinterpret_cast<__half2&>(b),
                        reinterpret_cast<__half2&>(c));
    return reinterpret_cast<unsigned&>(r);
}
__device__ __forceinline__ unsigned packh2(float a, float b) {
    __half2 h = __floats2half2_rn(a, b);
    return reinterpret_cast<unsigned&>(h);
}
__device__ __forceinline__ float2 h2f2(unsigned a) {
    return __half22float2(reinterpret_cast<__half2&>(a));
}

// ---------------------------------------------------------------------------
// Kernel 1: projections -> packed half scratch + transposed fp16 x.
// 128 blocks x 32 rows: weight loads amortized, 4 dots per thread.
// ---------------------------------------------------------------------------
#define SXS 65   // padded stride for sx (conflict-free transpose reads)
__global__ __launch_bounds__(256) void prep_kernel(
    const float* __restrict__ x,
    const float* __restrict__ Wt,
    const float* __restrict__ Wx,
    const float* __restrict__ bh)
{
    __shared__ float sWt[DD*UU];
    __shared__ float sWx[DD*UU];
    __shared__ float sx [32*SXS];
    __shared__ float sq [32][UU];
    __shared__ float sk [32][UU];

    int t = threadIdx.x;
    int row0 = blockIdx.x * 32;
    for (int i = t; i < DD*UU; i += 256) { sWt[i] = Wt[i]; sWx[i] = Wx[i]; }
    for (int i = t; i < 32*DD; i += 256) sx[(i >> 6)*SXS + (i & 63)] = x[row0*DD + i];
    __syncthreads();

    int u = t & 31;
    float bhu = bh[u];
    #pragma unroll
    for (int it = 0; it < 4; it++) {
        int r = (t >> 5) + it*8;
        float aq = 0.f, ak = 0.f;
        #pragma unroll
        for (int d = 0; d < DD; d++) {
            float xv = sx[r*SXS + d];
            aq = fmaf(xv, sWt[d*UU + u], aq);
            ak = fmaf(xv, sWx[d*UU + u], ak);
        }
        sq[r][u] = aq;
        sk[r][u] = ak + bhu;
    }
    __syncthreads();

    int b  = row0 >> 10;
    int j0 = row0 & 1023;

    {   // pack q: 32 rows x 16 half2; each thread 2
        int row = t >> 3, c = t & 7;
        g_qh[(row0 + row)*16 + c]     = packh2(sq[row][2*c],      sq[row][2*c+1]);
        g_qh[(row0 + row)*16 + c + 8] = packh2(sq[row][2*c + 16], sq[row][2*c+17]);
    }
    if (t < 128) {  // pack + transpose k': 32 rows x 4 chunks
        int rr = t >> 2, cc = t & 3;
        uint4 v;
        v.x = packh2(sk[rr][cc*8+0], sk[rr][cc*8+1]);
        v.y = packh2(sk[rr][cc*8+2], sk[rr][cc*8+3]);
        v.z = packh2(sk[rr][cc*8+4], sk[rr][cc*8+5]);
        v.w = packh2(sk[rr][cc*8+6], sk[rr][cc*8+7]);
        g_kpt[(b*4 + cc)*1024 + j0 + rr] = v;
    }
    {   // transposed fp16 x: g_xt[b][d][j0..j0+31]; 64 d x 4 j-groups
        int d = t >> 2, gj = (t & 3)*8;
        __half h[8];
        #pragma unroll
        for (int jj = 0; jj < 8; jj++) h[jj] = __float2half(sx[(gj + jj)*SXS + d]);
        *(uint4*)&g_xt[(b*DD + d)*LL + j0 + gj] = *(uint4*)h;
    }
}

// ---------------------------------------------------------------------------
// Kernel 2: scoring only. 2 rows per block (2048 blocks -> 2.77 waves, 92%
// slot utilization at 5 blocks/SM). Writes fp16 exp(e) + inv sums.
// ---------------------------------------------------------------------------
__global__ __launch_bounds__(256, 5) void score_kernel(
    const float* __restrict__ Wa)
{
    __shared__ unsigned swa2[16];
    __shared__ unsigned sq2[TI][16];
    __shared__ float    redv[TI][8];

    int t  = threadIdx.x;
    int bi = blockIdx.x;                  // 0..2047
    int b  = bi >> 9;
    int row0 = b*LL + (bi & 511)*TI;      // global row

    if (t < 16) swa2[t] = packh2(Wa[2*t], Wa[2*t+1]);
    if (t < 16*TI) sq2[t >> 4][t & 15] = g_qh[(row0 + (t >> 4))*16 + (t & 15)];
    __syncthreads();

    const uint4* kp = g_kpt + (b*4)*1024;

    float acc_e[4][TI];                   // [jj][r]
    #pragma unroll
    for (int jj = 0; jj < 4; jj++)
        #pragma unroll
        for (int r = 0; r < TI; r++) acc_e[jj][r] = 0.f;

    uint4 kv = kp[t];                     // rolling 1-ahead prefetch
    #pragma unroll
    for (int cc = 0; cc < 4; cc++) {
        unsigned qc[TI][4], wc[4];
        #pragma unroll
        for (int k = 0; k < 4; k++) {
            wc[k] = swa2[cc*4 + k];
            #pragma unroll
            for (int r = 0; r < TI; r++) qc[r][k] = sq2[r][cc*4 + k];
        }
        #pragma unroll
        for (int jj = 0; jj < 4; jj++) {
            unsigned kw[4] = {kv.x, kv.y, kv.z, kv.w};
            int nit = cc*4 + jj + 1;
            if (nit < 16)
                kv = kp[(nit >> 2)*1024 + (nit & 3)*256 + t];
            #pragma unroll
            for (int r = 0; r < TI; r++) {
                unsigned hacc = 0u;
                #pragma unroll
                for (int k = 0; k < 4; k++)
                    hacc = hfma2u(tanh2u(hadd2u(qc[r][k], kw[k])), wc[k], hacc);
                float2 f = h2f2(hacc);
                acc_e[jj][r] += f.x + f.y;
            }
        }
    }

    float s[TI];
    #pragma unroll
    for (int r = 0; r < TI; r++) s[r] = 0.f;
    #pragma unroll
    for (int jj = 0; jj < 4; jj++) {
        int j = jj*256 + t;
        #pragma unroll
        for (int r = 0; r < TI; r++) {
            float ex = __expf(acc_e[jj][r]);     // |e| <= sum|Wa|: no max pass
            s[r] += ex;
            g_P[(size_t)(row0 + r)*LL + j] = __float2half(ex);
        }
    }

    #pragma unroll
    for (int o = 16; o; o >>= 1)
        #pragma unroll
        for (int r = 0; r < TI; r++) s[r] += __shfl_xor_sync(0xffffffffu, s[r], o);
    if ((t & 31) == 0)
        #pragma unroll
        for (int r = 0; r < TI; r++) redv[r][t >> 5] = s[r];
    __syncthreads();
    if (t < TI) {
        float S = 0.f;
        #pragma unroll
        for (int w = 0; w < 8; w++) S += redv[t][w];
        g_inv[row0 + t] = 1.f / (S + 1e-8f);
    }
}

// ---------------------------------------------------------------------------
// Kernel 3: V = P @ X via HMMA m16n8k16, epilogue scales by inv.
// Block: 32 i-rows x 64 d for one b. 128 blocks, 256 threads (8 warps).
// ---------------------------------------------------------------------------
#define LDP 72   // padded half-stride (conflict-free LDS.32 frags)
__global__ __launch_bounds__(256) void gemm_kernel(float* __restrict__ out)
{
    __shared__ __half sP[32*LDP];
    __shared__ __half sX[64*LDP];
    __shared__ float  sInv[32];

    int t  = threadIdx.x;
    int bi = blockIdx.x;                  // 0..127
    int b  = bi >> 5;
    int i0 = (bi & 31) * 32;

    if (t < 32) sInv[t] = g_inv[b*LL + i0 + t];

    int warp = t >> 5, lane = t & 31;
    int g = lane >> 2, tg = lane & 3;
    int wi = warp >> 2, wd = warp & 3;    // 2 i-halves x 4 d-quarters

    float c[2][4] = {{0,0,0,0},{0,0,0,0}};

    const __half* Pg = g_P  + (size_t)(b*LL + i0)*LL;
    const __half* Xg = g_xt + (size_t)b*DD*LL;
    int prow = t >> 3, pcg = t & 7;

    for (int kc = 0; kc < 16; kc++) {
        int k0 = kc*64;
        __syncthreads();
        // stage P tile 32 x 64
        *(uint4*)&sP[prow*LDP + pcg*8] = *(const uint4*)&Pg[prow*LL + k0 + pcg*8];
        // stage Xt tile 64 x 64 (rows = d)
        #pragma unroll
        for (int it = 0; it < 2; it++) {
            int idx = t + it*256;
            int xr = idx >> 3, xcg = idx & 7;
            *(uint4*)&sX[xr*LDP + xcg*8] = *(const uint4*)&Xg[xr*LL + k0 + xcg*8];
        }
        __syncthreads();

        const unsigned* sP2 = (const unsigned*)sP;
        const unsigned* sX2 = (const unsigned*)sX;
        #pragma unroll
        for (int ks = 0; ks < 4; ks++) {
            int arow = wi*16 + g;
            int col  = ks*8 + tg;         // half2 index within row
            unsigned a0 = sP2[ arow   *(LDP/2) + col];
            unsigned a1 = sP2[(arow+8)*(LDP/2) + col];
            unsigned a2 = sP2[ arow   *(LDP/2) + col + 4];
            unsigned a3 = sP2[(arow+8)*(LDP/2) + col + 4];
            #pragma unroll
            for (int nh = 0; nh < 2; nh++) {
                int nrow = wd*16 + nh*8 + g;
                unsigned b0 = sX2[nrow*(LDP/2) + col];
                unsigned b1 = sX2[nrow*(LDP/2) + col + 4];
                asm volatile(
                    "mma.sync.aligned.m16n8k16.row.col.f32.f16.f16.f32 "
                    "{%0,%1,%2,%3}, {%4,%5,%6,%7}, {%8,%9}, {%0,%1,%2,%3};"
                    : "+f"(c[nh][0]), "+f"(c[nh][1]), "+f"(c[nh][2]), "+f"(c[nh][3])
                    : "r"(a0), "r"(a1), "r"(a2), "r"(a3), "r"(b0), "r"(b1));
            }
        }
    }

    // epilogue: scale by inv, store f32
    int irow = b*LL + i0 + wi*16 + g;
    float inv0 = sInv[wi*16 + g];
    float inv8 = sInv[wi*16 + g + 8];
    #pragma unroll
    for (int nh = 0; nh < 2; nh++) {
        int d = wd*16 + nh*8 + 2*tg;
        float2 v0 = { c[nh][0]*inv0, c[nh][1]*inv0 };
        float2 v1 = { c[nh][2]*inv8, c[nh][3]*inv8 };
        *(float2*)&out[(size_t) irow   *DD + d] = v0;
        *(float2*)&out[(size_t)(irow+8)*DD + d] = v1;
    }
}

// ---------------------------------------------------------------------------
extern "C" void kernel_launch(void* const* d_in, const int* in_sizes, int n_in,
                              void* d_out, int out_size)
{
    const float* x  = (const float*)d_in[0];
    const float* Wt = (const float*)d_in[1];
    const float* Wx = (const float*)d_in[2];
    const float* Wa = (const float*)d_in[3];
    const float* bh = (const float*)d_in[4];
    // d_in[5] = ba cancels in softmax; d_in[6] attention_width is dead code.

    prep_kernel <<<BB*LL/32, 256>>>(x, Wt, Wx, bh);
    score_kernel<<<BB*LL/TI, 256>>>(Wa);
    gemm_kernel <<<BB*LL/32, 256>>>((float*)d_out);
}

// round 11
// speedup vs baseline: 1.1524x; 1.1116x over previous
#include <cuda_runtime.h>
#include <cuda_fp16.h>

#define BB 4
#define LL 1024
#define DD 64
#define UU 32
#define TI 4

// Scratch (allocation-free): transposed half2-packed k' and packed q.
__device__ __align__(16) uint4    g_kpt[4*BB*LL];   // [(b*4+cc)*1024+j]: u[cc*8..+7]
__device__ __align__(16) unsigned g_qh [BB*LL*16];  // row*16+c : q u-pair (2c,2c+1)

__device__ __forceinline__ unsigned tanh2u(unsigned x) {
    unsigned y; asm("tanh.approx.f16x2 %0, %1;" : "=r"(y) : "r"(x)); return y;
}
__device__ __forceinline__ unsigned hadd2u(unsigned a, unsigned b) {
    __half2 r = __hadd2(reinterpret_cast<__half2&>(a), reinterpret_cast<__half2&>(b));
    return reinterpret_cast<unsigned&>(r);
}
__device__ __forceinline__ unsigned hfma2u(unsigned a, unsigned b, unsigned c) {
    __half2 r = __hfma2(reinterpret_cast<__half2&>(a), reinterpret_cast<__half2&>(b),
                        reinterpret_cast<__half2&>(c));
    return reinterpret_cast<unsigned&>(r);
}
__device__ __forceinline__ unsigned packh2(float a, float b) {
    __half2 h = __floats2half2_rn(a, b);
    return reinterpret_cast<unsigned&>(h);
}
__device__ __forceinline__ float2 h2f2(unsigned a) {
    return __half22float2(reinterpret_cast<__half2&>(a));
}
__device__ __forceinline__ unsigned long long ffma2(
    unsigned long long a, unsigned long long b, unsigned long long c) {
    unsigned long long d;
    asm("fma.rn.f32x2 %0, %1, %2, %3;" : "=l"(d) : "l"(a), "l"(b), "l"(c));
    return d;
}
__device__ __forceinline__ unsigned long long bcast2(float p) {
    unsigned long long d;
    asm("mov.b64 %0, {%1, %1};" : "=l"(d) : "f"(p));
    return d;
}
__device__ __forceinline__ unsigned long long packf2(float a, float b) {
    unsigned long long d;
    asm("mov.b64 %0, {%1, %2};" : "=l"(d) : "f"(a), "f"(b));
    return d;
}

// ---------------------------------------------------------------------------
// Kernel 1: projections (R5 version — measured fast). 8 rows per block.
// ---------------------------------------------------------------------------
__global__ __launch_bounds__(256) void prep_kernel(
    const float* __restrict__ x,
    const float* __restrict__ Wt,
    const float* __restrict__ Wx,
    const float* __restrict__ bh)
{
    __shared__ float sWt[DD*UU];
    __shared__ float sWx[DD*UU];
    __shared__ float sx [8*DD];
    __shared__ float sq [8][UU];
    __shared__ float sk [8][UU];
    int t = threadIdx.x;
    for (int idx = t; idx < DD*UU; idx += 256) { sWt[idx] = Wt[idx]; sWx[idx] = Wx[idx]; }
    int row0 = blockIdx.x * 8;
    for (int idx = t; idx < 8*DD; idx += 256) sx[idx] = x[row0*DD + idx];
    __syncthreads();

    int r = t >> 5, u = t & 31;
    float aq = 0.f, ak = 0.f;
    #pragma unroll
    for (int d = 0; d < DD; d++) {
        float xv = sx[r*DD + d];
        aq = fmaf(xv, sWt[d*UU + u], aq);
        ak = fmaf(xv, sWx[d*UU + u], ak);
    }
    sq[r][u] = aq;
    sk[r][u] = ak + bh[u];
    __syncthreads();

    int b  = row0 >> 10;
    int j0 = row0 & 1023;
    if (t < 128) {
        int rr = t >> 4, c = t & 15;
        g_qh[(row0 + rr)*16 + c] = packh2(sq[rr][2*c], sq[rr][2*c+1]);
    }
    if (t < 32) {
        int rr = t >> 2, cc = t & 3;
        uint4 v;
        v.x = packh2(sk[rr][cc*8+0], sk[rr][cc*8+1]);
        v.y = packh2(sk[rr][cc*8+2], sk[rr][cc*8+3]);
        v.z = packh2(sk[rr][cc*8+4], sk[rr][cc*8+5]);
        v.w = packh2(sk[rr][cc*8+6], sk[rr][cc*8+7]);
        g_kpt[(b*4 + cc)*1024 + j0 + rr] = v;
    }
}

// ---------------------------------------------------------------------------
// Kernel 2: fused scoring + softmax + gather, PHASE-MIXED over 256-j chunks:
// pass-1 (MUFU-heavy) and pass-2 (L1/FMA-heavy) alternate so the pipes
// overlap across co-resident blocks. Double-buffered p smem, 1 sync/chunk.
// ---------------------------------------------------------------------------
__global__ __launch_bounds__(256, 4) void attn_kernel(
    const float* __restrict__ x,
    const float* __restrict__ Wa,
    float* __restrict__ out)
{
    __shared__ float4   p_sh[2][256];     // double-buffered probs (8 KB)
    __shared__ float    vsh [TI*LL];      // pass-2 partials        (16 KB)
    __shared__ float    redv[TI][8];
    __shared__ unsigned swa2[16];
    __shared__ unsigned sq2[TI][16];

    int t  = threadIdx.x;
    int bi = blockIdx.x;                  // 0..1023
    int b  = bi >> 8;
    int row0 = b*LL + (bi & 255)*TI;

    if (t < 16) swa2[t] = packh2(Wa[2*t], Wa[2*t+1]);
    if (t < 64) sq2[t >> 4][t & 15] = g_qh[(row0 + (t >> 4))*16 + (t & 15)];
    __syncthreads();

    const uint4*  kp = g_kpt + (b*4)*1024;
    const float4* xb = (const float4*)(x + b*(LL*DD));
    int d4 = t & 15, g = t >> 4;          // pass-2 thread layout

    float s[TI] = {0.f, 0.f, 0.f, 0.f};
    unsigned long long a[TI][2];
    #pragma unroll
    for (int r = 0; r < TI; r++) { a[r][0] = 0ull; a[r][1] = 0ull; }

    #pragma unroll 1
    for (int ch = 0; ch < 4; ch++) {
        int jbase = ch*256;
        // ---- pass-1: p = exp(sum_u Wa tanh(q + k')) for j = jbase + t -----
        uint4 kv[4];
        #pragma unroll
        for (int cc = 0; cc < 4; cc++) kv[cc] = kp[cc*1024 + jbase + t];

        float acc[TI] = {0.f, 0.f, 0.f, 0.f};
        #pragma unroll
        for (int cc = 0; cc < 4; cc++) {
            unsigned kw[4] = {kv[cc].x, kv[cc].y, kv[cc].z, kv[cc].w};
            unsigned wc[4];
            #pragma unroll
            for (int k = 0; k < 4; k++) wc[k] = swa2[cc*4 + k];
            #pragma unroll
            for (int r = 0; r < TI; r++) {
                unsigned hacc = 0u;
                #pragma unroll
                for (int k = 0; k < 4; k++)
                    hacc = hfma2u(tanh2u(hadd2u(sq2[r][cc*4 + k], kw[k])), wc[k], hacc);
                float2 f = h2f2(hacc);
                acc[r] += f.x + f.y;
            }
        }
        float4 pj;
        float* pp = (float*)&pj;
        #pragma unroll
        for (int r = 0; r < TI; r++) {
            float ex = __expf(acc[r]);    // |e| <= sum|Wa|: no max pass needed
            pp[r] = ex;
            s[r] += ex;
        }
        p_sh[ch & 1][t] = pj;
        __syncthreads();                  // publish p(ch); prior-buffer reads done

        // ---- pass-2: a[r] += p[r][j] * x[j][d] for this chunk --------------
        #pragma unroll 4
        for (int jj = 0; jj < 16; jj++) {
            int jl = jj*16 + g;
            float4 xv = xb[(jbase + jl)*16 + d4];
            float4 pv = p_sh[ch & 1][jl];
            unsigned long long xlo = packf2(xv.x, xv.y);
            unsigned long long xhi = packf2(xv.z, xv.w);
            float* pq = (float*)&pv;
            #pragma unroll
            for (int r = 0; r < TI; r++) {
                unsigned long long p2 = bcast2(pq[r]);
                a[r][0] = ffma2(p2, xlo, a[r][0]);
                a[r][1] = ffma2(p2, xhi, a[r][1]);
            }
        }
        // no second sync: double buffer + next iteration's sync protect reuse
    }

    // --- row-sum reduce ------------------------------------------------------
    #pragma unroll
    for (int o = 16; o; o >>= 1)
        #pragma unroll
        for (int r = 0; r < TI; r++) s[r] += __shfl_xor_sync(0xffffffffu, s[r], o);
    if ((t & 31) == 0)
        #pragma unroll
        for (int r = 0; r < TI; r++) redv[r][t >> 5] = s[r];

    // --- stash pass-2 partials ----------------------------------------------
    #pragma unroll
    for (int r = 0; r < TI; r++) {
        float4 av;
        ((unsigned long long*)&av)[0] = a[r][0];
        ((unsigned long long*)&av)[1] = a[r][1];
        ((float4*)vsh)[r*256 + g*16 + d4] = av;
    }
    __syncthreads();

    // --- final combine: 256 threads = 4 rows x 64 d --------------------------
    {
        int r = t >> 6, d = t & 63;
        float S = 0.f;
        #pragma unroll
        for (int w = 0; w < 8; w++) S += redv[r][w];
        float inv = 1.f / (S + 1e-8f);
        float v = 0.f;
        #pragma unroll
        for (int gg = 0; gg < 16; gg++) v += vsh[r*LL + gg*64 + d];
        out[(row0 + r)*DD + d] = v * inv;
    }
}

// ---------------------------------------------------------------------------
extern "C" void kernel_launch(void* const* d_in, const int* in_sizes, int n_in,
                              void* d_out, int out_size)
{
    const float* x  = (const float*)d_in[0];
    const float* Wt = (const float*)d_in[1];
    const float* Wx = (const float*)d_in[2];
    const float* Wa = (const float*)d_in[3];
    const float* bh = (const float*)d_in[4];
    // d_in[5] = ba cancels in softmax; d_in[6] attention_width is dead code.

    prep_kernel<<<BB*LL/8, 256>>>(x, Wt, Wx, bh);
    attn_kernel<<<BB*LL/TI, 256>>>(x, Wa, (float*)d_out);
}